// round 3
// baseline (speedup 1.0000x reference)
#include <cuda_runtime.h>

// out[b] = dot(user_factors[users[b]], item_factors[items[b]]), D = 64, fp32.
//
// One warp handles 4 batch elements using LDG.128:
//   lane loads a float4 (16B); 16 lanes cover one 64-float row, so one
//   warp-wide LDG.128 fetches TWO rows (elements 2p and 2p+1).
//   4 row-loads total per warp (u01, v01, u23, v23), front-batched (MLP=4).
//   Per-lane dot4, then 4-round butterfly reduction within each 16-lane half.
// 1024 blocks x 128 threads -> ~7 CTAs/SM, 28 warps/SM.

#define D 64
#define ELEMS_PER_WARP 4
#define WARPS_PER_BLOCK 4
#define THREADS (WARPS_PER_BLOCK * 32)

__global__ __launch_bounds__(THREADS)
void mf_dot_kernel(const int* __restrict__ users,
                   const int* __restrict__ items,
                   const float* __restrict__ user_factors,
                   const float* __restrict__ item_factors,
                   float* __restrict__ out)
{
    int warp_id = (blockIdx.x * WARPS_PER_BLOCK) + (threadIdx.x >> 5);
    int lane = threadIdx.x & 31;
    int half = lane >> 4;        // 0: element 2p, 1: element 2p+1
    int sub  = lane & 15;        // float4 chunk within the row
    int base = warp_id * ELEMS_PER_WARP;

    // Element index this lane serves for pair p: base + 2p + half.
    int e0 = base + half;        // pair 0
    int e1 = base + 2 + half;    // pair 1

    // Front-batch index loads (each hits 1-2 sectors, L2-warm in steady state).
    int u0 = __ldg(&users[e0]);
    int i0 = __ldg(&items[e0]);
    int u1 = __ldg(&users[e1]);
    int i1 = __ldg(&items[e1]);

    // Front-batch 4 warp-wide LDG.128 row loads (each covers 2 rows).
    const float4* u0p = reinterpret_cast<const float4*>(user_factors + (long long)u0 * D);
    const float4* v0p = reinterpret_cast<const float4*>(item_factors + (long long)i0 * D);
    const float4* u1p = reinterpret_cast<const float4*>(user_factors + (long long)u1 * D);
    const float4* v1p = reinterpret_cast<const float4*>(item_factors + (long long)i1 * D);

    float4 a0 = __ldg(&u0p[sub]);
    float4 b0 = __ldg(&v0p[sub]);
    float4 a1 = __ldg(&u1p[sub]);
    float4 b1 = __ldg(&v1p[sub]);

    // Per-lane partial dot products (4 FMAs each).
    float acc0 = a0.x * b0.x;
    acc0 = fmaf(a0.y, b0.y, acc0);
    acc0 = fmaf(a0.z, b0.z, acc0);
    acc0 = fmaf(a0.w, b0.w, acc0);

    float acc1 = a1.x * b1.x;
    acc1 = fmaf(a1.y, b1.y, acc1);
    acc1 = fmaf(a1.z, b1.z, acc1);
    acc1 = fmaf(a1.w, b1.w, acc1);

    // Butterfly reduction within each 16-lane half (offsets 8,4,2,1 stay
    // inside the half). Two independent chains hide SHFL latency.
    #pragma unroll
    for (int off = 8; off > 0; off >>= 1) {
        acc0 += __shfl_xor_sync(0xFFFFFFFFu, acc0, off);
        acc1 += __shfl_xor_sync(0xFFFFFFFFu, acc1, off);
    }

    // Lane 0 holds (elem base, base+2); lane 16 holds (base+1, base+3).
    if (sub == 0) {
        out[base + half]     = acc0;
        out[base + 2 + half] = acc1;
    }
}

extern "C" void kernel_launch(void* const* d_in, const int* in_sizes, int n_in,
                              void* d_out, int out_size)
{
    const int*   users        = (const int*)  d_in[0];
    const int*   items        = (const int*)  d_in[1];
    const float* user_factors = (const float*)d_in[2];
    const float* item_factors = (const float*)d_in[3];
    float*       out          = (float*)      d_out;

    int batch = in_sizes[0];  // 16384
    int warps = batch / ELEMS_PER_WARP;                 // 4096
    int blocks = warps / WARPS_PER_BLOCK;               // 1024
    mf_dot_kernel<<<blocks, THREADS>>>(users, items, user_factors, item_factors, out);
}

// round 4
// speedup vs baseline: 1.0721x; 1.0721x over previous
#include <cuda_runtime.h>

// out[b] = dot(user_factors[users[b]], item_factors[items[b]]), D = 64, fp32.
//
// Structural-floor attack: 256 CTAs x 256 threads (2048 warps), 8 elements/warp.
//  - ONE predicated index LDG per warp: lanes 0-7 -> users[base..base+7],
//    lanes 8-15 -> items[base..base+7]; broadcast via SHFL (no extra L2 trips).
//  - 8 front-batched warp-wide LDG.128 row loads: 16 lanes cover one 64-float
//    row, so each load fetches TWO rows (elements 2p and 2p+1). MLP=8.
//  - 4 pairs reduced with 4 butterfly rounds each, 4 chains interleaved.

#define D 64
#define ELEMS_PER_WARP 8
#define WARPS_PER_BLOCK 8
#define THREADS (WARPS_PER_BLOCK * 32)

__global__ __launch_bounds__(THREADS)
void mf_dot_kernel(const int* __restrict__ users,
                   const int* __restrict__ items,
                   const float* __restrict__ user_factors,
                   const float* __restrict__ item_factors,
                   float* __restrict__ out)
{
    const int warp_id = (blockIdx.x * WARPS_PER_BLOCK) + (threadIdx.x >> 5);
    const int lane = threadIdx.x & 31;
    const int half = lane >> 4;      // 0: even elements, 1: odd elements
    const int sub  = lane & 15;      // float4 chunk within a row
    const int base = warp_id * ELEMS_PER_WARP;

    // ---- Stage 1: one warp-wide index load (lanes 0-7: users, 8-15: items) ----
    int myidx = 0;
    if (lane < 16) {
        const int* p = (lane < 8) ? (users + base + lane)
                                  : (items + base + (lane - 8));
        myidx = __ldg(p);
    }

    // Element served by this lane in pair p is (2p + half).
    // users index lives in lane (2p+half); items index in lane (8 + 2p+half).
    int uidx0 = __shfl_sync(0xFFFFFFFFu, myidx, 0 + half);
    int iidx0 = __shfl_sync(0xFFFFFFFFu, myidx, 8 + 0 + half);
    int uidx1 = __shfl_sync(0xFFFFFFFFu, myidx, 2 + half);
    int iidx1 = __shfl_sync(0xFFFFFFFFu, myidx, 8 + 2 + half);
    int uidx2 = __shfl_sync(0xFFFFFFFFu, myidx, 4 + half);
    int iidx2 = __shfl_sync(0xFFFFFFFFu, myidx, 8 + 4 + half);
    int uidx3 = __shfl_sync(0xFFFFFFFFu, myidx, 6 + half);
    int iidx3 = __shfl_sync(0xFFFFFFFFu, myidx, 8 + 6 + half);

    // ---- Stage 2: 8 independent LDG.128 row loads, front-batched (MLP=8) ----
    const float4* ua0 = reinterpret_cast<const float4*>(user_factors + (long long)uidx0 * D);
    const float4* va0 = reinterpret_cast<const float4*>(item_factors + (long long)iidx0 * D);
    const float4* ua1 = reinterpret_cast<const float4*>(user_factors + (long long)uidx1 * D);
    const float4* va1 = reinterpret_cast<const float4*>(item_factors + (long long)iidx1 * D);
    const float4* ua2 = reinterpret_cast<const float4*>(user_factors + (long long)uidx2 * D);
    const float4* va2 = reinterpret_cast<const float4*>(item_factors + (long long)iidx2 * D);
    const float4* ua3 = reinterpret_cast<const float4*>(user_factors + (long long)uidx3 * D);
    const float4* va3 = reinterpret_cast<const float4*>(item_factors + (long long)iidx3 * D);

    float4 a0 = __ldg(&ua0[sub]);
    float4 b0 = __ldg(&va0[sub]);
    float4 a1 = __ldg(&ua1[sub]);
    float4 b1 = __ldg(&va1[sub]);
    float4 a2 = __ldg(&ua2[sub]);
    float4 b2 = __ldg(&va2[sub]);
    float4 a3 = __ldg(&ua3[sub]);
    float4 b3 = __ldg(&va3[sub]);

    // ---- Stage 3: per-lane dot4, then 4 interleaved 16-lane reductions ----
    float acc0 = a0.x * b0.x;
    acc0 = fmaf(a0.y, b0.y, acc0); acc0 = fmaf(a0.z, b0.z, acc0); acc0 = fmaf(a0.w, b0.w, acc0);
    float acc1 = a1.x * b1.x;
    acc1 = fmaf(a1.y, b1.y, acc1); acc1 = fmaf(a1.z, b1.z, acc1); acc1 = fmaf(a1.w, b1.w, acc1);
    float acc2 = a2.x * b2.x;
    acc2 = fmaf(a2.y, b2.y, acc2); acc2 = fmaf(a2.z, b2.z, acc2); acc2 = fmaf(a2.w, b2.w, acc2);
    float acc3 = a3.x * b3.x;
    acc3 = fmaf(a3.y, b3.y, acc3); acc3 = fmaf(a3.z, b3.z, acc3); acc3 = fmaf(a3.w, b3.w, acc3);

    #pragma unroll
    for (int off = 8; off > 0; off >>= 1) {
        acc0 += __shfl_xor_sync(0xFFFFFFFFu, acc0, off);
        acc1 += __shfl_xor_sync(0xFFFFFFFFu, acc1, off);
        acc2 += __shfl_xor_sync(0xFFFFFFFFu, acc2, off);
        acc3 += __shfl_xor_sync(0xFFFFFFFFu, acc3, off);
    }

    // ---- Stage 4: lanes 0 and 16 store 4 results each (same 32B region) ----
    if (sub == 0) {
        out[base + 0 + half] = acc0;
        out[base + 2 + half] = acc1;
        out[base + 4 + half] = acc2;
        out[base + 6 + half] = acc3;
    }
}

extern "C" void kernel_launch(void* const* d_in, const int* in_sizes, int n_in,
                              void* d_out, int out_size)
{
    const int*   users        = (const int*)  d_in[0];
    const int*   items        = (const int*)  d_in[1];
    const float* user_factors = (const float*)d_in[2];
    const float* item_factors = (const float*)d_in[3];
    float*       out          = (float*)      d_out;

    int batch = in_sizes[0];                       // 16384
    int warps = batch / ELEMS_PER_WARP;            // 2048
    int blocks = warps / WARPS_PER_BLOCK;          // 256
    mf_dot_kernel<<<blocks, THREADS>>>(users, items, user_factors, item_factors, out);
}